// round 5
// baseline (speedup 1.0000x reference)
#include <cuda_runtime.h>

// LeadLagSignature depth-3, lead-lag of 16-point sliding patches.
// R4: occupancy push (64-reg cap -> 8 blocks/SM) + shfl instead of LDS for va.
// Thread (a, b) owns columns (b, b+8) of S2/S3 row a. 128 threads/block.

#define DIM 8
#define PATCH 16
#define NDIFF 15
#define LLD 16

__device__ __forceinline__ unsigned long long ffma2(unsigned long long a,
                                                    unsigned long long b,
                                                    unsigned long long c) {
    unsigned long long d;
    asm("fma.rn.f32x2 %0, %1, %2, %3;" : "=l"(d) : "l"(a), "l"(b), "l"(c));
    return d;
}

__device__ __forceinline__ unsigned long long bcast2(float f) {
    unsigned int r = __float_as_uint(f);
    unsigned long long d;
    asm("mov.b64 %0, {%1, %1};" : "=l"(d) : "r"(r));
    return d;
}

// ALEAD: whether row index a is in the lead half (warp-uniform: a = tid>>3
// spans 4 consecutive values per warp, all on one side of 8).
template <bool ALEAD>
__device__ __forceinline__ void sig_loop(const float* __restrict__ sd,
                                         int ai, int bi,
                                         unsigned long long* s3b,   // column b   (lead)
                                         unsigned long long* s3g,   // column b+8 (lag)
                                         float& s2b, float& s2g, float& s1a) {
    const float C2 = 0.5f;
    const float C3 = 1.0f / 6.0f;
#pragma unroll
    for (int t = 0; t < NDIFF; ++t) {
        const ulonglong2 pA = *reinterpret_cast<const ulonglong2*>(sd + t * 8);
        const ulonglong2 pB = *reinterpret_cast<const ulonglong2*>(sd + t * 8 + 4);
        const float vb = sd[t * 8 + bi];
        // lane `ai` of this warp holds v[ai] as its vb (bi = lane&7) -> shuffle
        const float va = __shfl_sync(0xffffffffu, vb, ai);

        float Fb, F2b, Fg, F2g;
        if (ALEAD) {
            // lead step: pa=va; pb: col b -> vb, col b+8 -> 0
            Fg = s2g;                                 // pb=0
            const float cs1 = C2 * s1a;
            const float u   = fmaf(C3, va, cs1);
            Fb  = fmaf(vb, u, s2b);
            const float w   = fmaf(C2, va, s1a);
            s2b = fmaf(vb, w, s2b);
            s1a += va;
            // lag step: pa=0; pb: col b -> 0, col b+8 -> vb
            F2b = s2b;                                // pb=0
            const float h   = C2 * s1a;
            F2g = fmaf(vb, h, s2g);
            s2g = fmaf(vb, s1a, s2g);
        } else {
            // lead step: pa=0; pb: col b -> vb, col b+8 -> 0
            const float cs1 = C2 * s1a;
            Fb  = fmaf(vb, cs1, s2b);
            s2b = fmaf(vb, s1a, s2b);
            Fg  = s2g;
            // lag step: pa=va; pb: col b -> 0, col b+8 -> vb
            F2b = s2b;
            const float u   = fmaf(C3, va, cs1);
            F2g = fmaf(vb, u, s2g);
            const float w   = fmaf(C2, va, s1a);
            s2g = fmaf(vb, w, s2g);
            s1a += va;
        }

        const unsigned long long Fbp  = bcast2(Fb);
        const unsigned long long F2bp = bcast2(F2b);
        const unsigned long long Fgp  = bcast2(Fg);
        const unsigned long long F2gp = bcast2(F2g);

        // column b
        s3b[0] = ffma2(Fbp,  pA.x, s3b[0]);
        s3b[1] = ffma2(Fbp,  pA.y, s3b[1]);
        s3b[2] = ffma2(Fbp,  pB.x, s3b[2]);
        s3b[3] = ffma2(Fbp,  pB.y, s3b[3]);
        s3b[4] = ffma2(F2bp, pA.x, s3b[4]);
        s3b[5] = ffma2(F2bp, pA.y, s3b[5]);
        s3b[6] = ffma2(F2bp, pB.x, s3b[6]);
        s3b[7] = ffma2(F2bp, pB.y, s3b[7]);
        // column b+8
        s3g[0] = ffma2(Fgp,  pA.x, s3g[0]);
        s3g[1] = ffma2(Fgp,  pA.y, s3g[1]);
        s3g[2] = ffma2(Fgp,  pB.x, s3g[2]);
        s3g[3] = ffma2(Fgp,  pB.y, s3g[3]);
        s3g[4] = ffma2(F2gp, pA.x, s3g[4]);
        s3g[5] = ffma2(F2gp, pA.y, s3g[5]);
        s3g[6] = ffma2(F2gp, pB.x, s3g[6]);
        s3g[7] = ffma2(F2gp, pB.y, s3g[7]);
    }
}

__global__ void __launch_bounds__(128, 8)
leadlag_sig_kernel(const float* __restrict__ x,
                   float* __restrict__ out1,
                   float* __restrict__ out2,
                   float* __restrict__ out3,
                   int seq_len)
{
    __shared__ __align__(16) float sd[NDIFF * DIM];

    const int i   = blockIdx.x;
    const int tid = threadIdx.x;

    if (tid < NDIFF * DIM) {
        int t = tid >> 3;
        int c = tid & 7;
        int r0 = i + t - (PATCH - 1);
        int r1 = r0 + 1;
        float p0 = (r0 >= 0) ? x[r0 * DIM + c] : 0.0f;
        float p1 = (r1 >= 0) ? x[r1 * DIM + c] : 0.0f;
        sd[tid] = p1 - p0;
    }
    __syncthreads();

    const int a  = tid >> 3;        // 0..15
    const int b  = tid & 7;         // lead column; lag column is b+8
    const int ai = a & 7;

    unsigned long long s3b[8], s3g[8];
#pragma unroll
    for (int k = 0; k < 8; ++k) { s3b[k] = 0ULL; s3g[k] = 0ULL; }
    float s2b = 0.0f, s2g = 0.0f, s1a = 0.0f;

    if (a < 8) {   // warp-uniform
        sig_loop<true >(sd, ai, b, s3b, s3g, s2b, s2g, s1a);
    } else {
        sig_loop<false>(sd, ai, b, s3b, s3g, s2b, s2g, s1a);
    }

    // ---- outputs ----
    if (b == 0) out1[i * LLD + a] = s1a;
    const int r2 = i * (LLD * LLD) + a * LLD + b;
    out2[r2]     = s2b;
    out2[r2 + 8] = s2g;

    float* base = out3 + (size_t)i * (LLD * LLD * LLD);
    ulonglong2* ob = reinterpret_cast<ulonglong2*>(base + (a * LLD + b) * LLD);
    ob[0] = make_ulonglong2(s3b[0], s3b[1]);
    ob[1] = make_ulonglong2(s3b[2], s3b[3]);
    ob[2] = make_ulonglong2(s3b[4], s3b[5]);
    ob[3] = make_ulonglong2(s3b[6], s3b[7]);
    ulonglong2* og = reinterpret_cast<ulonglong2*>(base + (a * LLD + b + 8) * LLD);
    og[0] = make_ulonglong2(s3g[0], s3g[1]);
    og[1] = make_ulonglong2(s3g[2], s3g[3]);
    og[2] = make_ulonglong2(s3g[4], s3g[5]);
    og[3] = make_ulonglong2(s3g[6], s3g[7]);
}

extern "C" void kernel_launch(void* const* d_in, const int* in_sizes, int n_in,
                              void* d_out, int out_size)
{
    const float* x = (const float*)d_in[0];
    const int seq_len = in_sizes[0] / DIM;

    float* out = (float*)d_out;
    float* out1 = out;
    float* out2 = out + (size_t)seq_len * LLD;
    float* out3 = out + (size_t)seq_len * LLD + (size_t)seq_len * LLD * LLD;

    leadlag_sig_kernel<<<seq_len, 128>>>(x, out1, out2, out3, seq_len);
}

// round 6
// speedup vs baseline: 1.4426x; 1.4426x over previous
#include <cuda_runtime.h>

// LeadLagSignature depth-3 via sliding-window Chen recursion.
// Block handles CHUNK consecutive positions: full 15-diff recursion for the
// first, then per position one combined left-removal (C = e^{-G} ⊗ e^{-L})
// plus the usual right-append of the two new increments.
// Thread (a, b) owns S2/S3 row a, columns b and b+8. 128 threads/block.

#define DIM 8
#define PATCH 16
#define NDIFF 15
#define LLD 16
#define CHUNK 8
#define NDT (NDIFF + CHUNK - 1)   // 22 diffs per block

typedef unsigned long long u64;

__device__ __forceinline__ u64 ffma2(u64 a, u64 b, u64 c) {
    u64 d;
    asm("fma.rn.f32x2 %0, %1, %2, %3;" : "=l"(d) : "l"(a), "l"(b), "l"(c));
    return d;
}

__device__ __forceinline__ u64 bcast2(float f) {
    unsigned int r = __float_as_uint(f);
    u64 d;
    asm("mov.b64 %0, {%1, %1};" : "=l"(d) : "r"(r));
    return d;
}

// Right-append of the two increments (lead then lag) of one diff vector dv.
// ALEAD: row a in lead half (warp-uniform).
template <bool ALEAD>
__device__ __forceinline__ void right_pair(const float* __restrict__ dv,
                                           int ai, int bi,
                                           u64* s3b, u64* s3g,
                                           float& s2b, float& s2g, float& s1a)
{
    const float C2 = 0.5f;
    const float C3 = 1.0f / 6.0f;
    const ulonglong2 pA = *reinterpret_cast<const ulonglong2*>(dv);
    const ulonglong2 pB = *reinterpret_cast<const ulonglong2*>(dv + 4);
    const float va = dv[ai];
    const float vb = dv[bi];

    float Fb, F2b, Fg, F2g;
    if (ALEAD) {
        Fg = s2g;
        const float cs1 = C2 * s1a;
        const float u   = fmaf(C3, va, cs1);
        Fb  = fmaf(vb, u, s2b);
        const float w   = fmaf(C2, va, s1a);
        s2b = fmaf(vb, w, s2b);
        s1a += va;
        F2b = s2b;
        const float h   = C2 * s1a;
        F2g = fmaf(vb, h, s2g);
        s2g = fmaf(vb, s1a, s2g);
    } else {
        const float cs1 = C2 * s1a;
        Fb  = fmaf(vb, cs1, s2b);
        s2b = fmaf(vb, s1a, s2b);
        Fg  = s2g;
        F2b = s2b;
        const float u   = fmaf(C3, va, cs1);
        F2g = fmaf(vb, u, s2g);
        const float w   = fmaf(C2, va, s1a);
        s2g = fmaf(vb, w, s2g);
        s1a += va;
    }

    const u64 Fbp  = bcast2(Fb);
    const u64 F2bp = bcast2(F2b);
    const u64 Fgp  = bcast2(Fg);
    const u64 F2gp = bcast2(F2g);

    s3b[0] = ffma2(Fbp,  pA.x, s3b[0]);
    s3b[1] = ffma2(Fbp,  pA.y, s3b[1]);
    s3b[2] = ffma2(Fbp,  pB.x, s3b[2]);
    s3b[3] = ffma2(Fbp,  pB.y, s3b[3]);
    s3b[4] = ffma2(F2bp, pA.x, s3b[4]);
    s3b[5] = ffma2(F2bp, pA.y, s3b[5]);
    s3b[6] = ffma2(F2bp, pB.x, s3b[6]);
    s3b[7] = ffma2(F2bp, pB.y, s3b[7]);
    s3g[0] = ffma2(Fgp,  pA.x, s3g[0]);
    s3g[1] = ffma2(Fgp,  pA.y, s3g[1]);
    s3g[2] = ffma2(Fgp,  pB.x, s3g[2]);
    s3g[3] = ffma2(Fgp,  pB.y, s3g[3]);
    s3g[4] = ffma2(F2gp, pA.x, s3g[4]);
    s3g[5] = ffma2(F2gp, pA.y, s3g[5]);
    s3g[6] = ffma2(F2gp, pB.x, s3g[6]);
    s3g[7] = ffma2(F2gp, pB.y, s3g[7]);
}

// Combined left-removal by C = e^{-G(d)} ⊗ e^{-L(d)}:
//   S1'      = S1 - vfull
//   S2'[a,c] = S2[a,c] - Da*S1[c] + m2(a,c)*Da*Dc
//   S3'[a,c,:] += C1[a]*S2old[c,:] + C2[a,c]*S1old[:] + C3[a,c,:]
// with m2 = {same half: 1/2, a lag & c lead: 1, a lead & c lag: 0} and
// C3[a,c,e] = -Da*Dc*De * m3, m3 nonzero iff h(a)>=h(c)>=h(e):
//   (0,0,0)=1/6, (1,1,1)=1/6, (1,0,0)=1/2, (1,1,0)=1/2.
template <bool ALEAD>
__device__ __forceinline__ void left_remove(const float* __restrict__ dOld,
                                            const float* __restrict__ s2rowb,
                                            const float* __restrict__ s2rowg,
                                            const float* __restrict__ s1old,
                                            int ai, int b,
                                            u64* s3b, u64* s3g,
                                            float& s2b, float& s2g, float& s1a)
{
    const float Da = dOld[ai];
    const float Db = dOld[b];           // note: Δ_{b+8} == Δ_b
    const ulonglong2 v0 = *reinterpret_cast<const ulonglong2*>(dOld);
    const ulonglong2 v1 = *reinterpret_cast<const ulonglong2*>(dOld + 4);
    const u64 C1 = bcast2(-Da);
    const float t = Da * Db;

    const ulonglong2 q0 = *reinterpret_cast<const ulonglong2*>(s1old);
    const ulonglong2 q1 = *reinterpret_cast<const ulonglong2*>(s1old + 4);
    const ulonglong2 q2 = *reinterpret_cast<const ulonglong2*>(s1old + 8);
    const ulonglong2 q3 = *reinterpret_cast<const ulonglong2*>(s1old + 12);
    const float S1b  = s1old[b];
    const float S1b8 = s1old[b + 8];

    const ulonglong2 rb0 = *reinterpret_cast<const ulonglong2*>(s2rowb);
    const ulonglong2 rb1 = *reinterpret_cast<const ulonglong2*>(s2rowb + 4);
    const ulonglong2 rb2 = *reinterpret_cast<const ulonglong2*>(s2rowb + 8);
    const ulonglong2 rb3 = *reinterpret_cast<const ulonglong2*>(s2rowb + 12);
    const ulonglong2 rg0 = *reinterpret_cast<const ulonglong2*>(s2rowg);
    const ulonglong2 rg1 = *reinterpret_cast<const ulonglong2*>(s2rowg + 4);
    const ulonglong2 rg2 = *reinterpret_cast<const ulonglong2*>(s2rowg + 8);
    const ulonglong2 rg3 = *reinterpret_cast<const ulonglong2*>(s2rowg + 12);

    // C1 ⊗ S2old term — both columns, all c-pairs
    s3b[0] = ffma2(C1, rb0.x, s3b[0]);
    s3b[1] = ffma2(C1, rb0.y, s3b[1]);
    s3b[2] = ffma2(C1, rb1.x, s3b[2]);
    s3b[3] = ffma2(C1, rb1.y, s3b[3]);
    s3b[4] = ffma2(C1, rb2.x, s3b[4]);
    s3b[5] = ffma2(C1, rb2.y, s3b[5]);
    s3b[6] = ffma2(C1, rb3.x, s3b[6]);
    s3b[7] = ffma2(C1, rb3.y, s3b[7]);
    s3g[0] = ffma2(C1, rg0.x, s3g[0]);
    s3g[1] = ffma2(C1, rg0.y, s3g[1]);
    s3g[2] = ffma2(C1, rg1.x, s3g[2]);
    s3g[3] = ffma2(C1, rg1.y, s3g[3]);
    s3g[4] = ffma2(C1, rg2.x, s3g[4]);
    s3g[5] = ffma2(C1, rg2.y, s3g[5]);
    s3g[6] = ffma2(C1, rg3.x, s3g[6]);
    s3g[7] = ffma2(C1, rg3.y, s3g[7]);

    if (ALEAD) {
        // col b (lead): C2 = t/2, K3(lead c) = -t/6, K3(lag c) = 0
        // col b+8 (lag): C2 = 0, K3 = 0 (h(a) < h(col))
        const u64 C2b = bcast2(0.5f * t);
        const u64 K3l = bcast2(-t * (1.0f / 6.0f));
        s3b[0] = ffma2(C2b, q0.x, s3b[0]);
        s3b[1] = ffma2(C2b, q0.y, s3b[1]);
        s3b[2] = ffma2(C2b, q1.x, s3b[2]);
        s3b[3] = ffma2(C2b, q1.y, s3b[3]);
        s3b[4] = ffma2(C2b, q2.x, s3b[4]);
        s3b[5] = ffma2(C2b, q2.y, s3b[5]);
        s3b[6] = ffma2(C2b, q3.x, s3b[6]);
        s3b[7] = ffma2(C2b, q3.y, s3b[7]);
        s3b[0] = ffma2(K3l, v0.x, s3b[0]);
        s3b[1] = ffma2(K3l, v0.y, s3b[1]);
        s3b[2] = ffma2(K3l, v1.x, s3b[2]);
        s3b[3] = ffma2(K3l, v1.y, s3b[3]);
        s2b = fmaf(-Da, S1b, fmaf(0.5f * Da, Db, s2b));
        s2g = fmaf(-Da, S1b8, s2g);
    } else {
        // col b (lead): C2 = t (m2(1,0)=1), K3(lead c) = -t/2, K3(lag c) = 0
        // col b+8 (lag): C2 = t/2, K3(lead c) = -t/2, K3(lag c) = -t/6
        const u64 C2b = bcast2(t);
        const u64 C2g = bcast2(0.5f * t);
        const u64 K3h = bcast2(-0.5f * t);
        const u64 K36 = bcast2(-t * (1.0f / 6.0f));
        s3b[0] = ffma2(C2b, q0.x, s3b[0]);
        s3b[1] = ffma2(C2b, q0.y, s3b[1]);
        s3b[2] = ffma2(C2b, q1.x, s3b[2]);
        s3b[3] = ffma2(C2b, q1.y, s3b[3]);
        s3b[4] = ffma2(C2b, q2.x, s3b[4]);
        s3b[5] = ffma2(C2b, q2.y, s3b[5]);
        s3b[6] = ffma2(C2b, q3.x, s3b[6]);
        s3b[7] = ffma2(C2b, q3.y, s3b[7]);
        s3g[0] = ffma2(C2g, q0.x, s3g[0]);
        s3g[1] = ffma2(C2g, q0.y, s3g[1]);
        s3g[2] = ffma2(C2g, q1.x, s3g[2]);
        s3g[3] = ffma2(C2g, q1.y, s3g[3]);
        s3g[4] = ffma2(C2g, q2.x, s3g[4]);
        s3g[5] = ffma2(C2g, q2.y, s3g[5]);
        s3g[6] = ffma2(C2g, q3.x, s3g[6]);
        s3g[7] = ffma2(C2g, q3.y, s3g[7]);
        s3b[0] = ffma2(K3h, v0.x, s3b[0]);
        s3b[1] = ffma2(K3h, v0.y, s3b[1]);
        s3b[2] = ffma2(K3h, v1.x, s3b[2]);
        s3b[3] = ffma2(K3h, v1.y, s3b[3]);
        s3g[0] = ffma2(K3h, v0.x, s3g[0]);
        s3g[1] = ffma2(K3h, v0.y, s3g[1]);
        s3g[2] = ffma2(K3h, v1.x, s3g[2]);
        s3g[3] = ffma2(K3h, v1.y, s3g[3]);
        s3g[4] = ffma2(K36, v0.x, s3g[4]);
        s3g[5] = ffma2(K36, v0.y, s3g[5]);
        s3g[6] = ffma2(K36, v1.x, s3g[6]);
        s3g[7] = ffma2(K36, v1.y, s3g[7]);
        s2b = fmaf(-Da, S1b, fmaf(Da, Db, s2b));
        s2g = fmaf(-Da, S1b8, fmaf(0.5f * Da, Db, s2g));
    }
    s1a -= Da;
}

__device__ __forceinline__ void store_pos(int i, int a, int b,
                                          float* __restrict__ out1,
                                          float* __restrict__ out2,
                                          float* __restrict__ out3,
                                          const u64* s3b, const u64* s3g,
                                          float s2b, float s2g, float s1a)
{
    if (b == 0) out1[i * LLD + a] = s1a;
    const int r2 = i * (LLD * LLD) + a * LLD + b;
    out2[r2]     = s2b;
    out2[r2 + 8] = s2g;

    float* base = out3 + (size_t)i * (LLD * LLD * LLD);
    ulonglong2* ob = reinterpret_cast<ulonglong2*>(base + (a * LLD + b) * LLD);
    ob[0] = make_ulonglong2(s3b[0], s3b[1]);
    ob[1] = make_ulonglong2(s3b[2], s3b[3]);
    ob[2] = make_ulonglong2(s3b[4], s3b[5]);
    ob[3] = make_ulonglong2(s3b[6], s3b[7]);
    ulonglong2* og = reinterpret_cast<ulonglong2*>(base + (a * LLD + b + 8) * LLD);
    og[0] = make_ulonglong2(s3g[0], s3g[1]);
    og[1] = make_ulonglong2(s3g[2], s3g[3]);
    og[2] = make_ulonglong2(s3g[4], s3g[5]);
    og[3] = make_ulonglong2(s3g[6], s3g[7]);
}

__global__ void __launch_bounds__(128, 5)
leadlag_sig_kernel(const float* __restrict__ x,
                   float* __restrict__ out1,
                   float* __restrict__ out2,
                   float* __restrict__ out3,
                   int seq_len)
{
    __shared__ __align__(16) float sd[NDT * DIM];
    __shared__ __align__(16) float s2buf[2][16][20];   // padded rows: conflict-free
    __shared__ __align__(16) float s1buf[2][16];

    const int p0  = blockIdx.x * CHUNK;
    const int tid = threadIdx.x;

    for (int j = tid; j < NDT * DIM; j += 128) {
        int t = j >> 3;
        int c = j & 7;
        int r0 = p0 + t - (PATCH - 1);
        int r1 = r0 + 1;
        float q0 = (r0 >= 0) ? x[r0 * DIM + c] : 0.0f;
        float q1 = (r1 >= 0) ? x[r1 * DIM + c] : 0.0f;
        sd[j] = q1 - q0;
    }
    __syncthreads();

    const int a  = tid >> 3;   // 0..15
    const int b  = tid & 7;    // lead column; lag column is b+8
    const int ai = a & 7;

    u64 s3b[8], s3g[8];
#pragma unroll
    for (int k = 0; k < 8; ++k) { s3b[k] = 0ULL; s3g[k] = 0ULL; }
    float s2b = 0.0f, s2g = 0.0f, s1a = 0.0f;

    // ---- full recursion for position p0 ----
    if (a < 8) {
#pragma unroll
        for (int t = 0; t < NDIFF; ++t)
            right_pair<true>(sd + t * 8, ai, b, s3b, s3g, s2b, s2g, s1a);
    } else {
#pragma unroll
        for (int t = 0; t < NDIFF; ++t)
            right_pair<false>(sd + t * 8, ai, b, s3b, s3g, s2b, s2g, s1a);
    }

    s2buf[0][a][b]     = s2b;
    s2buf[0][a][b + 8] = s2g;
    if (b == 0) s1buf[0][a] = s1a;
    __syncthreads();
    store_pos(p0, a, b, out1, out2, out3, s3b, s3g, s2b, s2g, s1a);

    // ---- slide ----
#pragma unroll 1
    for (int s = 1; s < CHUNK; ++s) {
        const int ob = (s - 1) & 1;
        const int nb = s & 1;
        const float* dOld = sd + (s - 1) * 8;
        const float* dNew = sd + (s + NDIFF - 1) * 8;
        if (a < 8) {
            left_remove<true >(dOld, &s2buf[ob][b][0], &s2buf[ob][b + 8][0],
                               &s1buf[ob][0], ai, b, s3b, s3g, s2b, s2g, s1a);
            right_pair<true >(dNew, ai, b, s3b, s3g, s2b, s2g, s1a);
        } else {
            left_remove<false>(dOld, &s2buf[ob][b][0], &s2buf[ob][b + 8][0],
                               &s1buf[ob][0], ai, b, s3b, s3g, s2b, s2g, s1a);
            right_pair<false>(dNew, ai, b, s3b, s3g, s2b, s2g, s1a);
        }
        s2buf[nb][a][b]     = s2b;
        s2buf[nb][a][b + 8] = s2g;
        if (b == 0) s1buf[nb][a] = s1a;
        __syncthreads();
        store_pos(p0 + s, a, b, out1, out2, out3, s3b, s3g, s2b, s2g, s1a);
    }
}

extern "C" void kernel_launch(void* const* d_in, const int* in_sizes, int n_in,
                              void* d_out, int out_size)
{
    const float* x = (const float*)d_in[0];
    const int seq_len = in_sizes[0] / DIM;

    float* out = (float*)d_out;
    float* out1 = out;
    float* out2 = out + (size_t)seq_len * LLD;
    float* out3 = out + (size_t)seq_len * LLD + (size_t)seq_len * LLD * LLD;

    leadlag_sig_kernel<<<seq_len / CHUNK, 128>>>(x, out1, out2, out3, seq_len);
}